// round 7
// baseline (speedup 1.0000x reference)
#include <cuda_runtime.h>
#include <cuda_bf16.h>

// OHEM loss, C=1 specialization:
//   ce == 0 exactly, so cls_loss == 0; hard-negative mining is dead code.
//   out = 0.2 * sum_{pos}(smoothL1(loc_preds - loc_targets)) / num_pos
//
// R7: branch-free PREDICATED loads (inline PTX @p ld.global.cs.v4.f32 with
// zero-initialized dests). All loads for 2 anchors front-batch before any
// compute (per-warp MLP 8 vs 4 for the branchy version), while predicated-off
// lanes still skip their 32B sectors (keeps the measured 6% line-skip saving).
// smooth_l1(0)=0 exactly, so skipped anchors contribute 0 without any mask.
// Single kernel; last-arriving block folds partials (ticket + threadfence).

#define NBLOCKS  1184   // 148 SMs * 8 blocks worth of CTAs (grid-stride)
#define NTHREADS 256
#define NWARPS   (NTHREADS / 32)

__device__ float g_partial_sum[NBLOCKS];
__device__ int   g_partial_cnt[NBLOCKS];
__device__ int   g_ticket = 0;          // self-resets each run; deterministic

__device__ __forceinline__ float smooth_l1(float d) {
    float ax = fabsf(d);
    return (ax < 1.0f) ? 0.5f * d * d : ax - 0.5f;
}

// Predicated 128-bit streaming load: no branch, no memory request when off.
// Destinations pre-zeroed so predicated-off lanes yield exact zeros.
__device__ __forceinline__ float4 ldcs128_pred(const float4* __restrict__ p,
                                               int pred) {
    float4 v = make_float4(0.0f, 0.0f, 0.0f, 0.0f);
    asm volatile(
        "{\n\t"
        ".reg .pred pp;\n\t"
        "setp.ne.s32 pp, %5, 0;\n\t"
        "@pp ld.global.cs.v4.f32 {%0,%1,%2,%3}, [%4];\n\t"
        "}"
        : "+f"(v.x), "+f"(v.y), "+f"(v.z), "+f"(v.w)
        : "l"(p), "r"(pred));
    return v;
}

__device__ __forceinline__ float pair_loss(float4 p0, float4 p1,
                                           float4 t0, float4 t1) {
    float s = smooth_l1(p0.x - t0.x);
    s += smooth_l1(p0.y - t0.y);
    s += smooth_l1(p0.z - t0.z);
    s += smooth_l1(p0.w - t0.w);
    s += smooth_l1(p1.x - t1.x);
    s += smooth_l1(p1.y - t1.y);
    s += smooth_l1(p1.z - t1.z);
    s += smooth_l1(p1.w - t1.w);
    return s;
}

__global__ __launch_bounds__(NTHREADS)
void ohem_fused_kernel(const float4* __restrict__ lp,   // loc_preds  (2 float4/anchor)
                       const float4* __restrict__ lt,   // loc_targets
                       const int*    __restrict__ ct,   // cls_targets
                       int nAnchors,
                       float* __restrict__ out)
{
    float sum = 0.0f;
    int   cnt = 0;

    const int stride  = gridDim.x * blockDim.x;
    const int stride2 = 2 * stride;
    int i = blockIdx.x * blockDim.x + threadIdx.x;

    // 2 anchors per iteration, ALL loads front-batched, zero branches in body.
    for (; i + stride < nAnchors; i += stride2) {
        int ta = __ldcs(ct + i);
        int tb = __ldcs(ct + i + stride);
        int pa = ta > 0;
        int pb = tb > 0;
        int j  = i + stride;

        float4 a0 = ldcs128_pred(lp + 2 * i,     pa);
        float4 a1 = ldcs128_pred(lp + 2 * i + 1, pa);
        float4 b0 = ldcs128_pred(lp + 2 * j,     pb);
        float4 b1 = ldcs128_pred(lp + 2 * j + 1, pb);
        float4 c0 = ldcs128_pred(lt + 2 * i,     pa);
        float4 c1 = ldcs128_pred(lt + 2 * i + 1, pa);
        float4 d0 = ldcs128_pred(lt + 2 * j,     pb);
        float4 d1 = ldcs128_pred(lt + 2 * j + 1, pb);

        // Predicated-off lanes hold zeros -> smooth_l1(0) = 0 exactly.
        sum += pair_loss(a0, a1, c0, c1);
        sum += pair_loss(b0, b1, d0, d1);
        cnt += pa + pb;
    }
    if (i < nAnchors) {
        int t  = __ldcs(ct + i);
        int pa = t > 0;
        float4 a0 = ldcs128_pred(lp + 2 * i,     pa);
        float4 a1 = ldcs128_pred(lp + 2 * i + 1, pa);
        float4 c0 = ldcs128_pred(lt + 2 * i,     pa);
        float4 c1 = ldcs128_pred(lt + 2 * i + 1, pa);
        sum += pair_loss(a0, a1, c0, c1);
        cnt += pa;
    }

    // intra-block tree reduction
    #pragma unroll
    for (int off = 16; off > 0; off >>= 1) {
        sum += __shfl_xor_sync(0xFFFFFFFFu, sum, off);
        cnt += __shfl_xor_sync(0xFFFFFFFFu, cnt, off);
    }

    __shared__ float ssum[NWARPS];
    __shared__ int   scnt[NWARPS];
    __shared__ bool  s_last;
    int lane = threadIdx.x & 31;
    int wid  = threadIdx.x >> 5;
    if (lane == 0) { ssum[wid] = sum; scnt[wid] = cnt; }
    __syncthreads();

    if (wid == 0) {
        float s = (lane < NWARPS) ? ssum[lane] : 0.0f;
        int   c = (lane < NWARPS) ? scnt[lane] : 0;
        #pragma unroll
        for (int off = 16; off > 0; off >>= 1) {
            s += __shfl_xor_sync(0xFFFFFFFFu, s, off);
            c += __shfl_xor_sync(0xFFFFFFFFu, c, off);
        }
        if (lane == 0) {
            g_partial_sum[blockIdx.x] = s;
            g_partial_cnt[blockIdx.x] = c;
            __threadfence();
            int ticket = atomicAdd(&g_ticket, 1);
            s_last = (ticket == gridDim.x - 1);
        }
    }
    __syncthreads();

    // last-arriving block folds all partials (fixed tree order: deterministic)
    if (s_last) {
        float fs = 0.0f;
        int   fc = 0;
        for (int k = threadIdx.x; k < NBLOCKS; k += NTHREADS) {
            fs += ((volatile float*)g_partial_sum)[k];
            fc += ((volatile int*)g_partial_cnt)[k];
        }
        #pragma unroll
        for (int off = 16; off > 0; off >>= 1) {
            fs += __shfl_xor_sync(0xFFFFFFFFu, fs, off);
            fc += __shfl_xor_sync(0xFFFFFFFFu, fc, off);
        }
        if (lane == 0) { ssum[wid] = fs; scnt[wid] = fc; }
        __syncthreads();
        if (wid == 0) {
            float s2 = (lane < NWARPS) ? ssum[lane] : 0.0f;
            int   c2 = (lane < NWARPS) ? scnt[lane] : 0;
            #pragma unroll
            for (int off = 16; off > 0; off >>= 1) {
                s2 += __shfl_xor_sync(0xFFFFFFFFu, s2, off);
                c2 += __shfl_xor_sync(0xFFFFFFFFu, c2, off);
            }
            if (lane == 0) {
                out[0] = 0.2f * s2 / (float)c2;   // cls term exactly 0 for C=1
                g_ticket = 0;                     // reset for next graph replay
            }
        }
    }
}

extern "C" void kernel_launch(void* const* d_in, const int* in_sizes, int n_in,
                              void* d_out, int out_size)
{
    // inputs: loc_preds [B,A,8] f32, loc_targets [B,A,8] f32,
    //         cls_preds [B,A,1] f32 (UNUSED), cls_targets [B,A] i32
    const float4* lp = (const float4*)d_in[0];
    const float4* lt = (const float4*)d_in[1];
    const int*    ct = (const int*)d_in[3];
    float* out = (float*)d_out;

    int nAnchors = in_sizes[3];      // 3,200,000

    ohem_fused_kernel<<<NBLOCKS, NTHREADS>>>(lp, lt, ct, nAnchors, out);
}